// round 4
// baseline (speedup 1.0000x reference)
#include <cuda_runtime.h>
#include <math.h>

// ---------------------------------------------------------------------------
// SE4: 4x4-patch squeeze-excite, batch-pipelined fused steps.
//   t: [B=8, C=64, H=256, W=256] fp32
//   pooled[b,(i*4+j)*64+c] = mean of 64x64 patch (i,j) of channel c
//   s = mish(pooled @ reduce_w^T + reduce_b)   [8,256]
//   g = sigmoid(s @ expand_w^T + expand_b)     [8,1024]
//   out = t * g (broadcast per patch/channel)
//
// Structure: pool0 (batch 0) ; step(b) for b=0..7 where step(b) =
//   [32 M-blocks: mlp(b)] || [256 P-blocks: pool(b+1)] ; then all gate(b).
// gate(b) reads t(b) from L2 (pooled in previous kernel) -> DRAM = read t once
// + write out once = 268 MB instead of 402 MB.
// ---------------------------------------------------------------------------

#define B_   8
#define C_   64
#define H_   256
#define W_   256
#define SQ_  256
#define GC_  (16 * C_)              // 1024
#define NPOOL (B_ * GC_)            // 8192
#define NTHREADS 256
#define M_BLOCKS 32
#define P_BLOCKS 256
#define G_BLOCKS (M_BLOCKS + P_BLOCKS)      // 288 << resident capacity
#define BATCH_F4 (C_ * H_ * W_ / 4)         // 1048576 float4 per batch

__device__ float g_ph0[NPOOL];      // half-patch partial sums (rows 0-31)
__device__ float g_ph1[NPOOL];      // half-patch partial sums (rows 32-63)
__device__ float g_s[B_ * SQ_];
__device__ float g_gates[NPOOL];
__device__ int   g_cnt1[B_];
__device__ int   g_cnt2[B_];

// ---------------------------------------------------------------------------
__device__ __forceinline__ float mishf(float x) {
    float sp = (x > 20.0f) ? x : log1pf(__expf(x));
    return x * tanhf(sp);
}
__device__ __forceinline__ float sigmoidf_(float x) {
    return 1.0f / (1.0f + __expf(-x));
}

// Pool one half-patch (32 rows x 64 cols) per warp. pw in [0, 2048).
// Coalesced: each instr covers 2 full rows (lane>>4 = row pair, lane&15 = col4).
__device__ __forceinline__ void pool_half_warp(const float* __restrict__ t,
                                               int bb, int pw, int lane) {
    int half = pw & 1;
    int p    = pw >> 1;             // 0..1023
    int c    = p >> 4;
    int ij   = p & 15;
    int i    = ij >> 2;
    int j    = ij & 3;

    const float* base = t + (((size_t)(bb * C_ + c) * H_ + i * 64 + half * 32) * W_ + j * 64);
    const float* q = base + (size_t)(lane >> 4) * W_ + (lane & 15) * 4;

    float a0 = 0.f, a1 = 0.f, a2 = 0.f, a3 = 0.f;
#pragma unroll
    for (int it = 0; it < 4; ++it) {
        float4 v0 = *reinterpret_cast<const float4*>(q + (size_t)(it * 8 + 0) * W_);
        float4 v1 = *reinterpret_cast<const float4*>(q + (size_t)(it * 8 + 2) * W_);
        float4 v2 = *reinterpret_cast<const float4*>(q + (size_t)(it * 8 + 4) * W_);
        float4 v3 = *reinterpret_cast<const float4*>(q + (size_t)(it * 8 + 6) * W_);
        a0 += (v0.x + v0.y) + (v0.z + v0.w);
        a1 += (v1.x + v1.y) + (v1.z + v1.w);
        a2 += (v2.x + v2.y) + (v2.z + v2.w);
        a3 += (v3.x + v3.y) + (v3.z + v3.w);
    }
    float acc = (a0 + a1) + (a2 + a3);
#pragma unroll
    for (int off = 16; off > 0; off >>= 1)
        acc += __shfl_down_sync(0xFFFFFFFFu, acc, off);
    if (lane == 0) {
        float* dst = half ? g_ph1 : g_ph0;
        dst[bb * GC_ + ij * C_ + c] = acc;   // raw sum; /4096 applied in mlp1
    }
}

// ---------------------------------------------------------------------------
// Lead-in: zero flags, pool batch 0. 256 blocks x 256 thr = 2048 warps.
// ---------------------------------------------------------------------------
__global__ void __launch_bounds__(NTHREADS) se4_pool0(const float* __restrict__ t) {
    if (blockIdx.x == 0 && threadIdx.x < 2 * B_) {
        if (threadIdx.x < B_) g_cnt1[threadIdx.x] = 0;
        else                  g_cnt2[threadIdx.x - B_] = 0;
    }
    int pw   = blockIdx.x * 8 + (threadIdx.x >> 5);   // 0..2047
    int lane = threadIdx.x & 31;
    pool_half_warp(t, 0, pw, lane);
}

// ---------------------------------------------------------------------------
// Fused step: mlp(b) on M blocks || pool(b+1) on P blocks, then all gate(b).
// ---------------------------------------------------------------------------
__global__ void __launch_bounds__(NTHREADS) se4_step(const float* __restrict__ t,
                                                     const float* __restrict__ reduce_w,
                                                     const float* __restrict__ reduce_b,
                                                     const float* __restrict__ expand_w,
                                                     const float* __restrict__ expand_b,
                                                     float* __restrict__ out,
                                                     int b) {
    int lane = threadIdx.x & 31;
    int warp = threadIdx.x >> 5;

    if (blockIdx.x < M_BLOCKS) {
        // ----- MLP role: 32 blocks = 256 warps -----
        int wg = blockIdx.x * 8 + warp;              // 0..255 = mlp1 output idx

        // mlp1: s[b,wg] = mish( dot(pooled[b,:], reduce_w[wg,:])/4096 + bias )
        {
            const float4* wrow = reinterpret_cast<const float4*>(reduce_w + (size_t)wg * GC_);
            const float4* p0   = reinterpret_cast<const float4*>(g_ph0 + (size_t)b * GC_);
            const float4* p1   = reinterpret_cast<const float4*>(g_ph1 + (size_t)b * GC_);
            float acc = 0.0f;
#pragma unroll
            for (int k4 = lane; k4 < GC_ / 4; k4 += 32) {
                float4 wv = wrow[k4];
                float4 x0 = p0[k4];
                float4 x1 = p1[k4];
                acc += wv.x * (x0.x + x1.x) + wv.y * (x0.y + x1.y)
                     + wv.z * (x0.z + x1.z) + wv.w * (x0.w + x1.w);
            }
#pragma unroll
            for (int off = 16; off > 0; off >>= 1)
                acc += __shfl_down_sync(0xFFFFFFFFu, acc, off);
            if (lane == 0)
                g_s[b * SQ_ + wg] = mishf(acc * (1.0f / 4096.0f) + reduce_b[wg]);
        }
        __threadfence();
        __syncthreads();
        if (threadIdx.x == 0) atomicAdd(&g_cnt1[b], 1);

        // wait for all 32 mlp1 blocks
        if (threadIdx.x == 0) {
            volatile int* v = &g_cnt1[b];
            while (*v < M_BLOCKS) __nanosleep(32);
        }
        __syncthreads();

        // mlp2: 4 outputs per warp (256 warps x 4 = 1024)
        const float4* srow = reinterpret_cast<const float4*>(g_s + (size_t)b * SQ_);
#pragma unroll
        for (int qq = 0; qq < 4; ++qq) {
            int o = wg + qq * 256;
            const float4* erow = reinterpret_cast<const float4*>(expand_w + (size_t)o * SQ_);
            float acc = 0.0f;
#pragma unroll
            for (int k4 = lane; k4 < SQ_ / 4; k4 += 32) {
                float4 wv = erow[k4];
                float4 sv = __ldcg(srow + k4);      // cross-SM: bypass L1
                acc += wv.x * sv.x + wv.y * sv.y + wv.z * sv.z + wv.w * sv.w;
            }
#pragma unroll
            for (int off = 16; off > 0; off >>= 1)
                acc += __shfl_down_sync(0xFFFFFFFFu, acc, off);
            if (lane == 0)
                g_gates[b * GC_ + o] = sigmoidf_(acc + expand_b[o]);
        }
        __threadfence();
        __syncthreads();
        if (threadIdx.x == 0) atomicAdd(&g_cnt2[b], 1);
    } else if (b + 1 < B_) {
        // ----- Pool role: 256 blocks = 2048 warps pool batch b+1 -----
        int pw = (blockIdx.x - M_BLOCKS) * 8 + warp;
        pool_half_warp(t, b + 1, pw, lane);
    }

    // ----- Gate role: all blocks gate batch b -----
    if (threadIdx.x == 0) {
        volatile int* v = &g_cnt2[b];
        while (*v < M_BLOCKS) __nanosleep(64);
    }
    __syncthreads();

    __shared__ float sg[GC_];
    for (int k = threadIdx.x; k < GC_; k += NTHREADS)
        sg[k] = __ldcg(&g_gates[b * GC_ + k]);
    __syncthreads();

    const float4* tb = reinterpret_cast<const float4*>(t) + (size_t)b * BATCH_F4;
    float4*       ob = reinterpret_cast<float4*>(out)     + (size_t)b * BATCH_F4;
    const size_t S = (size_t)G_BLOCKS * NTHREADS;          // 73728
    size_t k = (size_t)blockIdx.x * NTHREADS + threadIdx.x;

    for (; k + 3 * S < BATCH_F4; k += 4 * S) {
        size_t k0 = k, k1 = k + S, k2 = k + 2 * S, k3 = k + 3 * S;
        float4 v0 = __ldcs(tb + k0);
        float4 v1 = __ldcs(tb + k1);
        float4 v2 = __ldcs(tb + k2);
        float4 v3 = __ldcs(tb + k3);
        float g0 = sg[(((int)(k0 >> 6) & 255) >> 6) * 256 + (((int)(k0 & 63)) >> 4) * 64 + (((int)(k0 >> 14)) & 63)];
        float g1 = sg[(((int)(k1 >> 6) & 255) >> 6) * 256 + (((int)(k1 & 63)) >> 4) * 64 + (((int)(k1 >> 14)) & 63)];
        float g2 = sg[(((int)(k2 >> 6) & 255) >> 6) * 256 + (((int)(k2 & 63)) >> 4) * 64 + (((int)(k2 >> 14)) & 63)];
        float g3 = sg[(((int)(k3 >> 6) & 255) >> 6) * 256 + (((int)(k3 & 63)) >> 4) * 64 + (((int)(k3 >> 14)) & 63)];
        v0.x *= g0; v0.y *= g0; v0.z *= g0; v0.w *= g0;
        v1.x *= g1; v1.y *= g1; v1.z *= g1; v1.w *= g1;
        v2.x *= g2; v2.y *= g2; v2.z *= g2; v2.w *= g2;
        v3.x *= g3; v3.y *= g3; v3.z *= g3; v3.w *= g3;
        __stcs(ob + k0, v0);
        __stcs(ob + k1, v1);
        __stcs(ob + k2, v2);
        __stcs(ob + k3, v3);
    }
    for (; k < BATCH_F4; k += S) {
        float4 v = __ldcs(tb + k);
        float gg = sg[(((int)(k >> 6) & 255) >> 6) * 256 + (((int)(k & 63)) >> 4) * 64 + (((int)(k >> 14)) & 63)];
        v.x *= gg; v.y *= gg; v.z *= gg; v.w *= gg;
        __stcs(ob + k, v);
    }
}

// ---------------------------------------------------------------------------
extern "C" void kernel_launch(void* const* d_in, const int* in_sizes, int n_in,
                              void* d_out, int out_size) {
    const float* t        = (const float*)d_in[0];
    const float* reduce_w = (const float*)d_in[1];
    const float* reduce_b = (const float*)d_in[2];
    const float* expand_w = (const float*)d_in[3];
    const float* expand_b = (const float*)d_in[4];
    float* out = (float*)d_out;

    se4_pool0<<<P_BLOCKS, NTHREADS>>>(t);
    for (int b = 0; b < B_; ++b)
        se4_step<<<G_BLOCKS, NTHREADS>>>(t, reduce_w, reduce_b,
                                         expand_w, expand_b, out, b);
}

// round 5
// speedup vs baseline: 1.0018x; 1.0018x over previous
#include <cuda_runtime.h>
#include <math.h>

// ---------------------------------------------------------------------------
// SE4: 4x4-patch squeeze-excite, group-pipelined for L2 reuse.
//   t: [B=8, C=64, H=256, W=256] fp32 (134 MB). L2 = 126 MB.
//   Group = 4 batches = 67 MB -> fits L2.
//   K1: pool group0 (DRAM read 67 MB)
//   K2: mlp(g0) [32 blocks] || pool(g1) [1024 blocks], then ALL gate(g0)
//       gate reads t(g0) from L2, writes out streaming. DRAM = 67r + 67w.
//   K3: mlp(g1) || gate(g1). DRAM = 67w (reads from L2).
//   Total DRAM = 268 MB vs 402 MB for the naive two-pass structure.
// ---------------------------------------------------------------------------

#define B_   8
#define C_   64
#define H_   256
#define W_   256
#define SQ_  256
#define GC_  1024
#define NPOOL (B_ * GC_)            // 8192
#define GB_  4                      // batches per group
#define NG_  2                      // groups
#define NTHREADS 256
#define M_BLOCKS 32
#define P_BLOCKS 1024
#define FUSED_GRID 1184
#define BATCH_F4 (C_ * H_ * W_ / 4) // 1048576 float4 per batch
#define GROUP_F4 (GB_ * BATCH_F4)   // 4194304 float4 per group

__device__ float g_ph0[NPOOL];      // half-patch raw sums (rows 0-31)
__device__ float g_ph1[NPOOL];      // half-patch raw sums (rows 32-63)
__device__ float g_s[B_ * SQ_];
__device__ float g_gates[NPOOL];
__device__ int   g_cnt1[NG_];
__device__ int   g_cnt2[NG_];

// ---------------------------------------------------------------------------
__device__ __forceinline__ float mishf(float x) {
    float sp = (x > 20.0f) ? x : log1pf(__expf(x));
    return x * tanhf(sp);
}
__device__ __forceinline__ float sigmoidf_(float x) {
    return 1.0f / (1.0f + __expf(-x));
}

// Pool one half-patch (32 rows x 64 cols) per warp. pw in [0, 2048).
__device__ __forceinline__ void pool_half_warp(const float* __restrict__ t,
                                               int bb, int pw, int lane) {
    int half = pw & 1;
    int p    = pw >> 1;             // 0..1023
    int c    = p >> 4;
    int ij   = p & 15;
    int i    = ij >> 2;
    int j    = ij & 3;

    const float* base = t + (((size_t)(bb * C_ + c) * H_ + i * 64 + half * 32) * W_ + j * 64);
    const float* q = base + (size_t)(lane >> 4) * W_ + (lane & 15) * 4;

    float a0 = 0.f, a1 = 0.f, a2 = 0.f, a3 = 0.f;
#pragma unroll
    for (int it = 0; it < 4; ++it) {
        float4 v0 = *reinterpret_cast<const float4*>(q + (size_t)(it * 8 + 0) * W_);
        float4 v1 = *reinterpret_cast<const float4*>(q + (size_t)(it * 8 + 2) * W_);
        float4 v2 = *reinterpret_cast<const float4*>(q + (size_t)(it * 8 + 4) * W_);
        float4 v3 = *reinterpret_cast<const float4*>(q + (size_t)(it * 8 + 6) * W_);
        a0 += (v0.x + v0.y) + (v0.z + v0.w);
        a1 += (v1.x + v1.y) + (v1.z + v1.w);
        a2 += (v2.x + v2.y) + (v2.z + v2.w);
        a3 += (v3.x + v3.y) + (v3.z + v3.w);
    }
    float acc = (a0 + a1) + (a2 + a3);
#pragma unroll
    for (int off = 16; off > 0; off >>= 1)
        acc += __shfl_down_sync(0xFFFFFFFFu, acc, off);
    if (lane == 0) {
        float* dst = half ? g_ph1 : g_ph0;
        dst[bb * GC_ + ij * C_ + c] = acc;   // raw sum; /4096 in mlp1
    }
}

// Gate index within a group: k in [0, GROUP_F4)
// layout: [b_local(2)][c(6)][h(8)][w4(6)]; gate = b*1024 + i*256 + j*64 + c
__device__ __forceinline__ int gate_idx(size_t k) {
    return ((int)(k >> 20)) * 1024
         + (((int)(k >> 12)) & 3) * 256
         + (((int)(k >> 4))  & 3) * 64
         + (((int)(k >> 14)) & 63);
}

// ---------------------------------------------------------------------------
// K1: pool group 0 (8192 half-patches = 1024 blocks x 8 warps). Zero flags.
// ---------------------------------------------------------------------------
__global__ void __launch_bounds__(NTHREADS) se4_pool_g0(const float* __restrict__ t) {
    if (blockIdx.x == 0 && threadIdx.x < 2 * NG_) {
        if (threadIdx.x < NG_) g_cnt1[threadIdx.x] = 0;
        else                   g_cnt2[threadIdx.x - NG_] = 0;
    }
    int pw = blockIdx.x * 8 + (threadIdx.x >> 5);     // 0..8191
    pool_half_warp(t, pw >> 11, pw & 2047, threadIdx.x & 31);
}

// ---------------------------------------------------------------------------
// Fused step for group g:
//   blocks [0,32): full MLP for group g (spin among themselves)
//   blocks [32,1056): pool group g+1 (if any)
//   then ALL blocks: gate group g (t from L2, streaming stores)
// ---------------------------------------------------------------------------
__global__ void __launch_bounds__(NTHREADS) se4_fused(const float* __restrict__ t,
                                                      const float* __restrict__ reduce_w,
                                                      const float* __restrict__ reduce_b,
                                                      const float* __restrict__ expand_w,
                                                      const float* __restrict__ expand_b,
                                                      float* __restrict__ out,
                                                      int g) {
    __shared__ float sg[GB_ * GC_];   // 16 KB of gates for this group
    int lane = threadIdx.x & 31;
    int warp = threadIdx.x >> 5;

    if (blockIdx.x < M_BLOCKS) {
        // ---------------- MLP role: 32 blocks = 256 warps ----------------
        int wg = blockIdx.x * 8 + warp;              // 0..255 stage1 output

        // stage 1: s[b, wg] for the 4 batches of this group
        {
            const float4* wrow = reinterpret_cast<const float4*>(reduce_w + (size_t)wg * GC_);
            float acc[GB_] = {0.f, 0.f, 0.f, 0.f};
            for (int k4 = lane; k4 < GC_ / 4; k4 += 32) {
                float4 wv = wrow[k4];
#pragma unroll
                for (int bb = 0; bb < GB_; ++bb) {
                    float4 x0 = reinterpret_cast<const float4*>(g_ph0 + (size_t)(g * GB_ + bb) * GC_)[k4];
                    float4 x1 = reinterpret_cast<const float4*>(g_ph1 + (size_t)(g * GB_ + bb) * GC_)[k4];
                    acc[bb] += wv.x * (x0.x + x1.x) + wv.y * (x0.y + x1.y)
                             + wv.z * (x0.z + x1.z) + wv.w * (x0.w + x1.w);
                }
            }
#pragma unroll
            for (int bb = 0; bb < GB_; ++bb) {
                float a = acc[bb];
#pragma unroll
                for (int off = 16; off > 0; off >>= 1)
                    a += __shfl_down_sync(0xFFFFFFFFu, a, off);
                if (lane == 0)
                    g_s[(g * GB_ + bb) * SQ_ + wg] = mishf(a * (1.0f / 4096.0f) + reduce_b[wg]);
            }
        }
        __threadfence();
        __syncthreads();
        if (threadIdx.x == 0) {
            atomicAdd(&g_cnt1[g], 1);
            volatile int* v = &g_cnt1[g];
            while (*v < M_BLOCKS) __nanosleep(32);
        }
        __syncthreads();

        // stage 2: 4 outputs per warp x 4 batches
#pragma unroll
        for (int qq = 0; qq < 4; ++qq) {
            int o = wg + qq * 256;
            const float4* erow = reinterpret_cast<const float4*>(expand_w + (size_t)o * SQ_);
            float acc[GB_] = {0.f, 0.f, 0.f, 0.f};
            for (int k4 = lane; k4 < SQ_ / 4; k4 += 32) {
                float4 wv = erow[k4];
#pragma unroll
                for (int bb = 0; bb < GB_; ++bb) {
                    float4 sv = __ldcg(reinterpret_cast<const float4*>(g_s + (size_t)(g * GB_ + bb) * SQ_) + k4);
                    acc[bb] += wv.x * sv.x + wv.y * sv.y + wv.z * sv.z + wv.w * sv.w;
                }
            }
#pragma unroll
            for (int bb = 0; bb < GB_; ++bb) {
                float a = acc[bb];
#pragma unroll
                for (int off = 16; off > 0; off >>= 1)
                    a += __shfl_down_sync(0xFFFFFFFFu, a, off);
                if (lane == 0)
                    g_gates[(g * GB_ + bb) * GC_ + o] = sigmoidf_(a + expand_b[o]);
            }
        }
        __threadfence();
        __syncthreads();
        if (threadIdx.x == 0) atomicAdd(&g_cnt2[g], 1);
    } else if (blockIdx.x < M_BLOCKS + P_BLOCKS && g + 1 < NG_) {
        // ---------------- Pool role: pool group g+1 ----------------
        int pw = (blockIdx.x - M_BLOCKS) * 8 + warp;  // 0..8191
        pool_half_warp(t, (g + 1) * GB_ + (pw >> 11), pw & 2047, lane);
    }

    // ---------------- Gate role: everyone gates group g ----------------
    if (threadIdx.x == 0) {
        volatile int* v = &g_cnt2[g];
        while (*v < M_BLOCKS) __nanosleep(64);
    }
    __syncthreads();

    for (int k = threadIdx.x; k < GB_ * GC_; k += NTHREADS)
        sg[k] = __ldcg(&g_gates[g * GB_ * GC_ + k]);
    __syncthreads();

    const float4* tg = reinterpret_cast<const float4*>(t) + (size_t)g * GROUP_F4;
    float4*       og = reinterpret_cast<float4*>(out)     + (size_t)g * GROUP_F4;
    const size_t S = (size_t)gridDim.x * NTHREADS;
    size_t k = (size_t)blockIdx.x * NTHREADS + threadIdx.x;

    for (; k + 3 * S < GROUP_F4; k += 4 * S) {
        size_t k0 = k, k1 = k + S, k2 = k + 2 * S, k3 = k + 3 * S;
        float4 v0 = __ldcs(tg + k0);
        float4 v1 = __ldcs(tg + k1);
        float4 v2 = __ldcs(tg + k2);
        float4 v3 = __ldcs(tg + k3);
        float g0 = sg[gate_idx(k0)];
        float g1 = sg[gate_idx(k1)];
        float g2 = sg[gate_idx(k2)];
        float g3 = sg[gate_idx(k3)];
        v0.x *= g0; v0.y *= g0; v0.z *= g0; v0.w *= g0;
        v1.x *= g1; v1.y *= g1; v1.z *= g1; v1.w *= g1;
        v2.x *= g2; v2.y *= g2; v2.z *= g2; v2.w *= g2;
        v3.x *= g3; v3.y *= g3; v3.z *= g3; v3.w *= g3;
        __stcs(og + k0, v0);
        __stcs(og + k1, v1);
        __stcs(og + k2, v2);
        __stcs(og + k3, v3);
    }
    for (; k < GROUP_F4; k += S) {
        float4 v = __ldcs(tg + k);
        float gg = sg[gate_idx(k)];
        v.x *= gg; v.y *= gg; v.z *= gg; v.w *= gg;
        __stcs(og + k, v);
    }
}

// ---------------------------------------------------------------------------
extern "C" void kernel_launch(void* const* d_in, const int* in_sizes, int n_in,
                              void* d_out, int out_size) {
    const float* t        = (const float*)d_in[0];
    const float* reduce_w = (const float*)d_in[1];
    const float* reduce_b = (const float*)d_in[2];
    const float* expand_w = (const float*)d_in[3];
    const float* expand_b = (const float*)d_in[4];
    float* out = (float*)d_out;

    se4_pool_g0<<<1024, NTHREADS>>>(t);
    se4_fused<<<FUSED_GRID, NTHREADS>>>(t, reduce_w, reduce_b, expand_w, expand_b, out, 0);
    se4_fused<<<FUSED_GRID, NTHREADS>>>(t, reduce_w, reduce_b, expand_w, expand_b, out, 1);
}

// round 6
// speedup vs baseline: 1.4392x; 1.4365x over previous
#include <cuda_runtime.h>
#include <math.h>

// ---------------------------------------------------------------------------
// SE4: 4x4-patch squeeze-excite, group-pipelined (NO intra-kernel sync).
//   t: [B=8, C=64, H=256, W=256] fp32 (134 MB), L2 = 126 MB.
//   Groups: {0,1,2}, {3,4,5}, {6,7}  (50+50+34 MB).
//   pool(G0) ; mlp(G0) ; [pool(G1) || gate(G0)] ; mlp(G1) ;
//   [pool(G2) || gate(G1)] ; mlp(G2) ; gate(G2)
//   gate(Gk) reads t(Gk) from L2 (left there by the pool role one kernel
//   earlier); out writes are streaming (.stcs). DRAM ~= 268 MB total.
// ---------------------------------------------------------------------------

#define B_   8
#define C_   64
#define H_   256
#define W_   256
#define SQ_  256
#define GC_  1024
#define NPOOL (B_ * GC_)
#define NT   256
#define BATCH_F4 (C_ * H_ * W_ / 4)       // 1048576 = 2^20 float4 per batch
#define GATE_BLOCKS 1024

__device__ float g_pooled[NPOOL];
__device__ float g_s[B_ * SQ_];
__device__ float g_gates[NPOOL];

// ---------------------------------------------------------------------------
__device__ __forceinline__ float mishf(float x) {
    float sp = (x > 20.0f) ? x : log1pf(__expf(x));
    return x * tanhf(sp);
}
__device__ __forceinline__ float sigmoidf_(float x) {
    return 1.0f / (1.0f + __expf(-x));
}

// Pool one full 64x64 patch per warp. pwarp in [0, nb*1024).
__device__ __forceinline__ void pool_patch(const float* __restrict__ t,
                                           int b0, int pwarp, int lane) {
    int b  = b0 + (pwarp >> 10);
    int r  = pwarp & 1023;
    int c  = r >> 4;
    int ij = r & 15;
    int i  = ij >> 2;
    int j  = ij & 3;

    const float* base = t + (((size_t)(b * C_ + c) * H_ + i * 64) * W_ + j * 64);
    const float* p = base + (size_t)(lane >> 4) * W_ + (lane & 15) * 4;

    float a0 = 0.f, a1 = 0.f, a2 = 0.f, a3 = 0.f;
#pragma unroll
    for (int it = 0; it < 8; ++it) {
        float4 v0 = *reinterpret_cast<const float4*>(p + (size_t)(it * 8 + 0) * W_);
        float4 v1 = *reinterpret_cast<const float4*>(p + (size_t)(it * 8 + 2) * W_);
        float4 v2 = *reinterpret_cast<const float4*>(p + (size_t)(it * 8 + 4) * W_);
        float4 v3 = *reinterpret_cast<const float4*>(p + (size_t)(it * 8 + 6) * W_);
        a0 += (v0.x + v0.y) + (v0.z + v0.w);
        a1 += (v1.x + v1.y) + (v1.z + v1.w);
        a2 += (v2.x + v2.y) + (v2.z + v2.w);
        a3 += (v3.x + v3.y) + (v3.z + v3.w);
    }
    float acc = (a0 + a1) + (a2 + a3);
#pragma unroll
    for (int off = 16; off > 0; off >>= 1)
        acc += __shfl_down_sync(0xFFFFFFFFu, acc, off);
    if (lane == 0)
        g_pooled[b * GC_ + ij * C_ + c] = acc * (1.0f / 4096.0f);
}

// ---------------------------------------------------------------------------
// K: pool only (first group). grid = nb*128 blocks.
// ---------------------------------------------------------------------------
__global__ void __launch_bounds__(NT) se4_pool(const float* __restrict__ t, int b0) {
    pool_patch(t, b0, blockIdx.x * 8 + (threadIdx.x >> 5), threadIdx.x & 31);
}

// ---------------------------------------------------------------------------
// K: mlp stage 1 for batches [b0, b0+nb). One warp per (b,out). grid = nb*32.
// ---------------------------------------------------------------------------
__global__ void __launch_bounds__(NT) se4_mlp1(const float* __restrict__ reduce_w,
                                               const float* __restrict__ reduce_b,
                                               int b0) {
    int lw   = blockIdx.x * 8 + (threadIdx.x >> 5);
    int lane = threadIdx.x & 31;
    int b    = b0 + (lw >> 8);
    int out  = lw & 255;

    const float4* wrow = reinterpret_cast<const float4*>(reduce_w + (size_t)out * GC_);
    const float4* prow = reinterpret_cast<const float4*>(g_pooled + (size_t)b * GC_);

    float acc = 0.0f;
#pragma unroll
    for (int k4 = lane; k4 < GC_ / 4; k4 += 32) {
        float4 wv = wrow[k4];
        float4 pv = prow[k4];
        acc += wv.x * pv.x + wv.y * pv.y + wv.z * pv.z + wv.w * pv.w;
    }
#pragma unroll
    for (int off = 16; off > 0; off >>= 1)
        acc += __shfl_down_sync(0xFFFFFFFFu, acc, off);
    if (lane == 0)
        g_s[b * SQ_ + out] = mishf(acc + reduce_b[out]);
}

// ---------------------------------------------------------------------------
// K: mlp stage 2 for batches [b0, b0+nb). One warp per (b,out). grid = nb*128.
// ---------------------------------------------------------------------------
__global__ void __launch_bounds__(NT) se4_mlp2(const float* __restrict__ expand_w,
                                               const float* __restrict__ expand_b,
                                               int b0) {
    int lw   = blockIdx.x * 8 + (threadIdx.x >> 5);
    int lane = threadIdx.x & 31;
    int b    = b0 + (lw >> 10);
    int out  = lw & 1023;

    const float4* wrow = reinterpret_cast<const float4*>(expand_w + (size_t)out * SQ_);
    const float4* srow = reinterpret_cast<const float4*>(g_s + (size_t)b * SQ_);

    float acc = 0.0f;
#pragma unroll
    for (int k4 = lane; k4 < SQ_ / 4; k4 += 32) {
        float4 wv = wrow[k4];
        float4 sv = srow[k4];
        acc += wv.x * sv.x + wv.y * sv.y + wv.z * sv.z + wv.w * sv.w;
    }
#pragma unroll
    for (int off = 16; off > 0; off >>= 1)
        acc += __shfl_down_sync(0xFFFFFFFFu, acc, off);
    if (lane == 0)
        g_gates[b * GC_ + out] = sigmoidf_(acc + expand_b[out]);
}

// ---------------------------------------------------------------------------
// K: gatepool — two independent roles, no synchronization.
//   blocks [0, pool_nb*128): pool batches [pool_b0, pool_b0+pool_nb) (DRAM,
//     default cache policy -> fills L2 for the NEXT gatepool kernel)
//   blocks [pool_nb*128, +1024): gate batches [gate_b0, gate_b0+gate_nb)
//     (reads hit L2 from the previous kernel's pool role; .cs demotes after
//     use; .stcs streaming writes)
// ---------------------------------------------------------------------------
__global__ void __launch_bounds__(NT) se4_gatepool(const float* __restrict__ t,
                                                   float* __restrict__ out,
                                                   int gate_b0, int gate_nb,
                                                   int pool_b0, int pool_nb) {
    int lane = threadIdx.x & 31;
    int poolBlocks = pool_nb * 128;

    if ((int)blockIdx.x < poolBlocks) {
        pool_patch(t, pool_b0, blockIdx.x * 8 + (threadIdx.x >> 5), lane);
        return;
    }

    // ---- gate role ----
    int gb = blockIdx.x - poolBlocks;                 // 0..1023
    const float4* tb = reinterpret_cast<const float4*>(t)  + (size_t)gate_b0 * BATCH_F4;
    float4*       ob = reinterpret_cast<float4*>(out)      + (size_t)gate_b0 * BATCH_F4;
    const float*  gbase = g_gates + gate_b0 * GC_;
    const size_t total = (size_t)gate_nb * BATCH_F4;
    const size_t S = (size_t)GATE_BLOCKS * NT;        // 262144
    size_t k = (size_t)gb * NT + threadIdx.x;

    for (; k + 3 * S < total; k += 4 * S) {
        size_t k0 = k, k1 = k + S, k2 = k + 2 * S, k3 = k + 3 * S;
        float4 v0 = __ldcs(tb + k0);
        float4 v1 = __ldcs(tb + k1);
        float4 v2 = __ldcs(tb + k2);
        float4 v3 = __ldcs(tb + k3);
        float g0 = __ldg(gbase + ((int)(k0 >> 20)) * 1024 + (((int)(k0 >> 12)) & 3) * 256 + (((int)(k0 >> 4)) & 3) * 64 + (((int)(k0 >> 14)) & 63));
        float g1 = __ldg(gbase + ((int)(k1 >> 20)) * 1024 + (((int)(k1 >> 12)) & 3) * 256 + (((int)(k1 >> 4)) & 3) * 64 + (((int)(k1 >> 14)) & 63));
        float g2 = __ldg(gbase + ((int)(k2 >> 20)) * 1024 + (((int)(k2 >> 12)) & 3) * 256 + (((int)(k2 >> 4)) & 3) * 64 + (((int)(k2 >> 14)) & 63));
        float g3 = __ldg(gbase + ((int)(k3 >> 20)) * 1024 + (((int)(k3 >> 12)) & 3) * 256 + (((int)(k3 >> 4)) & 3) * 64 + (((int)(k3 >> 14)) & 63));
        v0.x *= g0; v0.y *= g0; v0.z *= g0; v0.w *= g0;
        v1.x *= g1; v1.y *= g1; v1.z *= g1; v1.w *= g1;
        v2.x *= g2; v2.y *= g2; v2.z *= g2; v2.w *= g2;
        v3.x *= g3; v3.y *= g3; v3.z *= g3; v3.w *= g3;
        __stcs(ob + k0, v0);
        __stcs(ob + k1, v1);
        __stcs(ob + k2, v2);
        __stcs(ob + k3, v3);
    }
    for (; k < total; k += S) {
        float4 v = __ldcs(tb + k);
        float gg = __ldg(gbase + ((int)(k >> 20)) * 1024 + (((int)(k >> 12)) & 3) * 256 + (((int)(k >> 4)) & 3) * 64 + (((int)(k >> 14)) & 63));
        v.x *= gg; v.y *= gg; v.z *= gg; v.w *= gg;
        __stcs(ob + k, v);
    }
}

// ---------------------------------------------------------------------------
extern "C" void kernel_launch(void* const* d_in, const int* in_sizes, int n_in,
                              void* d_out, int out_size) {
    const float* t        = (const float*)d_in[0];
    const float* reduce_w = (const float*)d_in[1];
    const float* reduce_b = (const float*)d_in[2];
    const float* expand_w = (const float*)d_in[3];
    const float* expand_b = (const float*)d_in[4];
    float* out = (float*)d_out;

    // Group sizes: G0 = {0,1,2}, G1 = {3,4,5}, G2 = {6,7}
    se4_pool<<<3 * 128, NT>>>(t, 0);
    se4_mlp1<<<3 * 32,  NT>>>(reduce_w, reduce_b, 0);
    se4_mlp2<<<3 * 128, NT>>>(expand_w, expand_b, 0);

    se4_gatepool<<<3 * 128 + GATE_BLOCKS, NT>>>(t, out, 0, 3, 3, 3);
    se4_mlp1<<<3 * 32,  NT>>>(reduce_w, reduce_b, 3);
    se4_mlp2<<<3 * 128, NT>>>(expand_w, expand_b, 3);

    se4_gatepool<<<2 * 128 + GATE_BLOCKS, NT>>>(t, out, 3, 3, 6, 2);
    se4_mlp1<<<2 * 32,  NT>>>(reduce_w, reduce_b, 6);
    se4_mlp2<<<2 * 128, NT>>>(expand_w, expand_b, 6);

    se4_gatepool<<<GATE_BLOCKS, NT>>>(t, out, 6, 2, 0, 0);
}